// round 14
// baseline (speedup 1.0000x reference)
#include <cuda_runtime.h>
#include <cuda_fp16.h>
#include <stdint.h>

#define N_NODES_MAX 100000
#define N_EDGES_MAX 1600000
#define IN_FEAT 64
#define OUT_FEAT 64
#define NUM_BASES 4
#define NUM_RELS 8
#define P2_COLS (NUM_RELS * OUT_FEAT)      // 512
#define WCAT_COLS (P2_COLS + OUT_FEAT)     // 576
#define WCAT_ELEMS (IN_FEAT * WCAT_COLS)   // 36864

#define SCAN_T 1024
#define SCAN_NB ((N_NODES_MAX + SCAN_T - 1) / SCAN_T)   // 98

// Scratch
__device__ __half g_proj2[(size_t)N_NODES_MAX * P2_COLS];   // ~102.4 MB
__device__ __half g_wcat[IN_FEAT * WCAT_COLS];
__device__ int    g_count[N_NODES_MAX];
__device__ int    g_offset[N_NODES_MAX];
__device__ int    g_cursor[N_NODES_MAX];
__device__ int2   g_edata[N_EDGES_MAX];     // dst-sorted {src|etype<<20, norm}
// Decoupled-lookback scan state
__device__ volatile int g_tile_status[SCAN_NB];   // 0=pending 1=agg 2=prefix
__device__ volatile int g_tile_agg[SCAN_NB];
__device__ volatile int g_tile_pref[SCAN_NB];

// ---------------------------------------------------------------------------
// Prep kernel: zero counts + build Wcat + reset scan tile state (one launch)
// ---------------------------------------------------------------------------
__global__ void prep_kernel(const float* __restrict__ weight,
                            const float* __restrict__ w_comp,
                            const float* __restrict__ loop_w,
                            int n_nodes)
{
    int idx = blockIdx.x * blockDim.x + threadIdx.x;
    if (idx < n_nodes) g_count[idx] = 0;
    if (idx < SCAN_NB) g_tile_status[idx] = 0;
    if (idx < WCAT_ELEMS) {
        int k = idx / WCAT_COLS;
        int n = idx % WCAT_COLS;
        float v;
        if (n < P2_COLS) {
            int r = n >> 6, o = n & 63;
            v = 0.0f;
            #pragma unroll
            for (int b = 0; b < NUM_BASES; ++b)
                v += w_comp[r * NUM_BASES + b] * weight[((size_t)b * 64 + k) * 64 + o];
        } else {
            v = loop_w[(size_t)k * 64 + (n - P2_COLS)];
        }
        g_wcat[idx] = __float2half_rn(v);
    }
}

// ---------------------------------------------------------------------------
__device__ __forceinline__ uint32_t smem_u32(const void* p) {
    return (uint32_t)__cvta_generic_to_shared(p);
}

#define LDSM_X4(r0, r1, r2, r3, addr)                                          \
    asm volatile("ldmatrix.sync.aligned.m8n8.x4.shared.b16 {%0,%1,%2,%3}, [%4];" \
                 : "=r"(r0), "=r"(r1), "=r"(r2), "=r"(r3) : "r"(addr))

#define LDSM_X4_T(r0, r1, r2, r3, addr)                                        \
    asm volatile("ldmatrix.sync.aligned.m8n8.x4.trans.shared.b16 {%0,%1,%2,%3}, [%4];" \
                 : "=r"(r0), "=r"(r1), "=r"(r2), "=r"(r3) : "r"(addr))

#define MMA_16816(d, a, b)                                                     \
    asm volatile("mma.sync.aligned.m16n8k16.row.col.f32.f16.f16.f32 "          \
                 "{%0,%1,%2,%3}, {%4,%5,%6,%7}, {%8,%9}, {%0,%1,%2,%3};"       \
                 : "+f"(d[0]), "+f"(d[1]), "+f"(d[2]), "+f"(d[3])              \
                 : "r"(a[0]), "r"(a[1]), "r"(a[2]), "r"(a[3]),                 \
                   "r"(b[0]), "r"(b[1]))

// ---------------------------------------------------------------------------
// Kernel A: proj2 (fp16) + out-init (fp32) via HMMA (R13 exact:
//   per-pass B, staged copy-out, embedded grid-stride dst-histogram)
// ---------------------------------------------------------------------------
#define SA_STRIDE 72
#define SBP_STRIDE 72
#define SS_STRIDE 72

#define SMEM_A_OFF 0
#define SMEM_B_OFF (128 * SA_STRIDE)
#define SMEM_S_OFF (128 * SA_STRIDE + 64 * SBP_STRIDE)
#define SMEM_HALVES (128 * SA_STRIDE + 64 * SBP_STRIDE + 128 * SS_STRIDE)
#define SMEM_BYTES (SMEM_HALVES * 2)   // 46080 B

__global__ __launch_bounds__(256, 3) void rgcn_mma_kernel(
    const float* __restrict__ feat,
    const float* __restrict__ h_bias,
    const int*   __restrict__ dst,
    float* __restrict__ out,
    int n_nodes, int n_edges)
{
    extern __shared__ __align__(16) __half dyn[];
    __half* sA = dyn + SMEM_A_OFF;
    __half* sB = dyn + SMEM_B_OFF;
    __half* sS = dyn + SMEM_S_OFF;

    const int tid = threadIdx.x;
    const int row0 = blockIdx.x * 128;
    const bool fullTile = (row0 + 128 <= n_nodes);

    // --- Embedded histogram: fire-and-forget REDs, independent of GEMM ---
    {
        int quads = (n_edges + 3) >> 2;
        for (int q = blockIdx.x * 256 + tid; q < quads; q += gridDim.x * 256) {
            int e0 = q * 4;
            if (e0 + 4 <= n_edges) {
                int4 d = __ldg((const int4*)(dst + e0));
                atomicAdd(&g_count[d.x], 1);
                atomicAdd(&g_count[d.y], 1);
                atomicAdd(&g_count[d.z], 1);
                atomicAdd(&g_count[d.w], 1);
            } else {
                for (int e = e0; e < n_edges; ++e)
                    atomicAdd(&g_count[__ldg(&dst[e])], 1);
            }
        }
    }

    // Load A tile (128 x 64), fp32 -> fp16
    #pragma unroll
    for (int i = tid; i < 128 * 32; i += 256) {
        int r = i >> 5;
        int cpair = i & 31;
        int row = row0 + r;
        float2 f = (row < n_nodes)
                     ? *(const float2*)&feat[(size_t)row * IN_FEAT + cpair * 2]
                     : make_float2(0.0f, 0.0f);
        *(__half2*)&sA[r * SA_STRIDE + cpair * 2] = __floats2half2_rn(f.x, f.y);
    }

    const int warp = tid >> 5;
    const int lane = tid & 31;
    const int wr = warp >> 1;
    const int wc = warp & 1;
    const int lrow = lane & 15;
    const int lcol = (lane >> 4) << 3;
    const int g   = lane >> 2;
    const int tig = lane & 3;

    for (int cp = 0; cp < 9; ++cp) {
        __syncthreads();
        #pragma unroll
        for (int i = tid; i < 512; i += 256) {
            int r = i >> 3;
            int ch = i & 7;
            *(uint4*)&sB[r * SBP_STRIDE + ch * 8] =
                *(const uint4*)&g_wcat[(size_t)r * WCAT_COLS + cp * 64 + ch * 8];
        }
        __syncthreads();

        float acc[2][4][4];
        #pragma unroll
        for (int mi = 0; mi < 2; ++mi)
            #pragma unroll
            for (int nj = 0; nj < 4; ++nj)
                #pragma unroll
                for (int q = 0; q < 4; ++q)
                    acc[mi][nj][q] = 0.0f;

        #pragma unroll
        for (int ks = 0; ks < 4; ++ks) {
            uint32_t a[2][4];
            #pragma unroll
            for (int mi = 0; mi < 2; ++mi) {
                const __half* p = &sA[(wr * 32 + mi * 16 + lrow) * SA_STRIDE
                                      + ks * 16 + lcol];
                LDSM_X4(a[mi][0], a[mi][1], a[mi][2], a[mi][3], smem_u32(p));
            }
            uint32_t b[4][2];
            #pragma unroll
            for (int np = 0; np < 2; ++np) {
                const __half* p = &sB[(ks * 16 + lrow) * SBP_STRIDE
                                      + wc * 32 + np * 16 + lcol];
                uint32_t r0, r1, r2, r3;
                LDSM_X4_T(r0, r1, r2, r3, smem_u32(p));
                b[np * 2 + 0][0] = r0; b[np * 2 + 0][1] = r1;
                b[np * 2 + 1][0] = r2; b[np * 2 + 1][1] = r3;
            }
            #pragma unroll
            for (int mi = 0; mi < 2; ++mi)
                #pragma unroll
                for (int nj = 0; nj < 4; ++nj)
                    MMA_16816(acc[mi][nj], a[mi], b[nj]);
        }

        if (cp < 8) {
            __syncthreads();
            #pragma unroll
            for (int mi = 0; mi < 2; ++mi) {
                int rta = wr * 32 + mi * 16 + g;
                int rtb = rta + 8;
                #pragma unroll
                for (int nj = 0; nj < 4; ++nj) {
                    int col = wc * 32 + nj * 8 + tig * 2;
                    *(__half2*)&sS[rta * SS_STRIDE + col] =
                        __floats2half2_rn(acc[mi][nj][0], acc[mi][nj][1]);
                    *(__half2*)&sS[rtb * SS_STRIDE + col] =
                        __floats2half2_rn(acc[mi][nj][2], acc[mi][nj][3]);
                }
            }
            __syncthreads();
            if (fullTile) {
                #pragma unroll
                for (int i = tid; i < 1024; i += 256) {
                    int r = i >> 3;
                    int ch = i & 7;
                    uint4 v = *(const uint4*)&sS[r * SS_STRIDE + ch * 8];
                    *(uint4*)&g_proj2[(size_t)(row0 + r) * P2_COLS
                                      + cp * OUT_FEAT + ch * 8] = v;
                }
            } else {
                #pragma unroll
                for (int i = tid; i < 1024; i += 256) {
                    int r = i >> 3;
                    int ch = i & 7;
                    int row = row0 + r;
                    if (row < n_nodes) {
                        uint4 v = *(const uint4*)&sS[r * SS_STRIDE + ch * 8];
                        *(uint4*)&g_proj2[(size_t)row * P2_COLS
                                          + cp * OUT_FEAT + ch * 8] = v;
                    }
                }
            }
        } else {
            #pragma unroll
            for (int mi = 0; mi < 2; ++mi) {
                int ra = row0 + wr * 32 + mi * 16 + g;
                int rb = ra + 8;
                #pragma unroll
                for (int nj = 0; nj < 4; ++nj) {
                    int col = wc * 32 + nj * 8 + tig * 2;
                    float b0 = h_bias[col];
                    float b1 = h_bias[col + 1];
                    if (ra < n_nodes)
                        *(float2*)&out[(size_t)ra * OUT_FEAT + col] =
                            make_float2(acc[mi][nj][0] + b0, acc[mi][nj][1] + b1);
                    if (rb < n_nodes)
                        *(float2*)&out[(size_t)rb * OUT_FEAT + col] =
                            make_float2(acc[mi][nj][2] + b0, acc[mi][nj][3] + b1);
                }
            }
        }
    }
}

// ---------------------------------------------------------------------------
// Single-pass decoupled-lookback exclusive scan over g_count -> g_offset/cursor
// All SCAN_NB blocks (<=148) are co-resident, so the lookback spin terminates.
// ---------------------------------------------------------------------------
__global__ __launch_bounds__(SCAN_T) void scan_fused_kernel(int n_nodes)
{
    __shared__ int sh[SCAN_T];
    __shared__ int s_base;

    const int bid = blockIdx.x;
    const int tidx = threadIdx.x;
    const int i = bid * SCAN_T + tidx;

    int c = (i < n_nodes) ? g_count[i] : 0;
    sh[tidx] = c;
    __syncthreads();
    #pragma unroll
    for (int off = 1; off < SCAN_T; off <<= 1) {
        int v = (tidx >= off) ? sh[tidx - off] : 0;
        __syncthreads();
        sh[tidx] += v;
        __syncthreads();
    }
    int total = sh[SCAN_T - 1];

    if (tidx == 0) {
        if (bid == 0) {
            g_tile_pref[0] = total;
            __threadfence();
            g_tile_status[0] = 2;
            s_base = 0;
        } else {
            g_tile_agg[bid] = total;
            __threadfence();
            g_tile_status[bid] = 1;
            int base = 0;
            int j = bid - 1;
            while (j >= 0) {
                int s;
                do { s = g_tile_status[j]; } while (s == 0);
                __threadfence();
                if (s == 2) { base += g_tile_pref[j]; break; }
                base += g_tile_agg[j];
                --j;
            }
            g_tile_pref[bid] = base + total;
            __threadfence();
            g_tile_status[bid] = 2;
            s_base = base;
        }
    }
    __syncthreads();

    if (i < n_nodes) {
        int o = sh[tidx] - c + s_base;   // exclusive
        g_offset[i] = o;
        g_cursor[i] = o;
    }
}

// ---------------------------------------------------------------------------
__global__ void scatter_kernel(const int* __restrict__ src,
                               const int* __restrict__ dst,
                               const int* __restrict__ etypes,
                               const float* __restrict__ norm,
                               int n_edges)
{
    int i = blockIdx.x * blockDim.x + threadIdx.x;
    int e0 = i * 4;
    if (e0 + 4 <= n_edges) {
        int4 s = __ldg((const int4*)(src + e0));
        int4 d = __ldg((const int4*)(dst + e0));
        int4 t = __ldg((const int4*)(etypes + e0));
        float4 nm = __ldg((const float4*)(norm + e0));
        int p0 = atomicAdd(&g_cursor[d.x], 1);
        int p1 = atomicAdd(&g_cursor[d.y], 1);
        int p2 = atomicAdd(&g_cursor[d.z], 1);
        int p3 = atomicAdd(&g_cursor[d.w], 1);
        g_edata[p0] = make_int2(s.x | (t.x << 20), __float_as_int(nm.x));
        g_edata[p1] = make_int2(s.y | (t.y << 20), __float_as_int(nm.y));
        g_edata[p2] = make_int2(s.z | (t.z << 20), __float_as_int(nm.z));
        g_edata[p3] = make_int2(s.w | (t.w << 20), __float_as_int(nm.w));
    } else if (e0 < n_edges) {
        for (int e = e0; e < n_edges; ++e) {
            int d = __ldg(&dst[e]);
            int pos = atomicAdd(&g_cursor[d], 1);
            g_edata[pos] = make_int2(__ldg(&src[e]) | (__ldg(&etypes[e]) << 20),
                                     __float_as_int(__ldg(&norm[e])));
        }
    }
}

// ---------------------------------------------------------------------------
// Kernel 4: per-node aggregation, 8 lanes/node, uint4 gathers (R8 exact)
// ---------------------------------------------------------------------------
__device__ __forceinline__ void acc_msg(float4& a, float4& b, uint4 raw, float nm)
{
    float2 f0 = __half22float2(*reinterpret_cast<__half2*>(&raw.x));
    float2 f1 = __half22float2(*reinterpret_cast<__half2*>(&raw.y));
    float2 f2 = __half22float2(*reinterpret_cast<__half2*>(&raw.z));
    float2 f3 = __half22float2(*reinterpret_cast<__half2*>(&raw.w));
    a.x += f0.x * nm; a.y += f0.y * nm; a.z += f1.x * nm; a.w += f1.y * nm;
    b.x += f2.x * nm; b.y += f2.y * nm; b.z += f3.x * nm; b.w += f3.y * nm;
}

__global__ __launch_bounds__(256) void agg_kernel(
    float* __restrict__ out, int n_nodes)
{
    int gidx = blockIdx.x * 256 + threadIdx.x;
    int node = gidx >> 3;
    int lane = gidx & 7;
    if (node >= n_nodes) return;

    int start = __ldg(&g_offset[node]);
    int deg   = __ldg(&g_count[node]);

    float4 accA = *(float4*)&out[(size_t)node * OUT_FEAT + lane * 8];
    float4 accB = *(float4*)&out[(size_t)node * OUT_FEAT + lane * 8 + 4];

    int j = 0;
    for (; j + 4 <= deg; j += 4) {
        int2 e0 = __ldg(&g_edata[start + j + 0]);
        int2 e1 = __ldg(&g_edata[start + j + 1]);
        int2 e2 = __ldg(&g_edata[start + j + 2]);
        int2 e3 = __ldg(&g_edata[start + j + 3]);
        uint4 r0 = __ldg((const uint4*)(g_proj2 +
            ((size_t)(e0.x & 0xFFFFF) * P2_COLS + (e0.x >> 20) * OUT_FEAT + lane * 8)));
        uint4 r1 = __ldg((const uint4*)(g_proj2 +
            ((size_t)(e1.x & 0xFFFFF) * P2_COLS + (e1.x >> 20) * OUT_FEAT + lane * 8)));
        uint4 r2 = __ldg((const uint4*)(g_proj2 +
            ((size_t)(e2.x & 0xFFFFF) * P2_COLS + (e2.x >> 20) * OUT_FEAT + lane * 8)));
        uint4 r3 = __ldg((const uint4*)(g_proj2 +
            ((size_t)(e3.x & 0xFFFFF) * P2_COLS + (e3.x >> 20) * OUT_FEAT + lane * 8)));
        acc_msg(accA, accB, r0, __int_as_float(e0.y));
        acc_msg(accA, accB, r1, __int_as_float(e1.y));
        acc_msg(accA, accB, r2, __int_as_float(e2.y));
        acc_msg(accA, accB, r3, __int_as_float(e3.y));
    }
    for (; j < deg; ++j) {
        int2 ed = __ldg(&g_edata[start + j]);
        uint4 raw = __ldg((const uint4*)(g_proj2 +
            ((size_t)(ed.x & 0xFFFFF) * P2_COLS + (ed.x >> 20) * OUT_FEAT + lane * 8)));
        acc_msg(accA, accB, raw, __int_as_float(ed.y));
    }

    *(float4*)&out[(size_t)node * OUT_FEAT + lane * 8]     = accA;
    *(float4*)&out[(size_t)node * OUT_FEAT + lane * 8 + 4] = accB;
}

// ---------------------------------------------------------------------------
extern "C" void kernel_launch(void* const* d_in, const int* in_sizes, int n_in,
                              void* d_out, int out_size)
{
    const float* feat    = (const float*)d_in[0];
    const int*   src     = (const int*)d_in[1];
    const int*   dst     = (const int*)d_in[2];
    const int*   etypes  = (const int*)d_in[3];
    const float* norm    = (const float*)d_in[4];
    const float* weight  = (const float*)d_in[5];
    const float* w_comp  = (const float*)d_in[6];
    const float* h_bias  = (const float*)d_in[7];
    const float* loop_w  = (const float*)d_in[8];
    float*       out     = (float*)d_out;

    int n_nodes = in_sizes[0] / IN_FEAT;
    int n_edges = in_sizes[1];

    static bool attrSet = false;
    if (!attrSet) {
        cudaFuncSetAttribute(rgcn_mma_kernel,
                             cudaFuncAttributeMaxDynamicSharedMemorySize, SMEM_BYTES);
        attrSet = true;
    }

    // Phase 0: zero counters + Wcat + scan state (one launch)
    int prep_elems = (n_nodes > WCAT_ELEMS) ? n_nodes : WCAT_ELEMS;
    prep_kernel<<<(prep_elems + 255) / 256, 256>>>(weight, w_comp, loop_w, n_nodes);

    // Phase 1: HMMA GEMM with embedded dst-histogram
    rgcn_mma_kernel<<<(n_nodes + 127) / 128, 256, SMEM_BYTES>>>(
        feat, h_bias, dst, out, n_nodes, n_edges);

    // Phase 2: single-pass scan, then scatter
    int nb = (n_nodes + SCAN_T - 1) / SCAN_T;
    scan_fused_kernel<<<nb, SCAN_T>>>(n_nodes);
    int hthreads = (n_edges + 3) / 4;
    scatter_kernel<<<(hthreads + 255) / 256, 256>>>(src, dst, etypes, norm, n_edges);

    // Phase 3: atomic-free aggregation
    long long total_threads = (long long)n_nodes * 8;
    agg_kernel<<<(int)((total_threads + 255) / 256), 256>>>(out, n_nodes);
}

// round 15
// speedup vs baseline: 1.0649x; 1.0649x over previous
#include <cuda_runtime.h>
#include <cuda_fp16.h>
#include <stdint.h>

#define N_NODES_MAX 100000
#define N_EDGES_MAX 1600000
#define IN_FEAT 64
#define OUT_FEAT 64
#define NUM_BASES 4
#define NUM_RELS 8
#define P2_COLS (NUM_RELS * OUT_FEAT)      // 512
#define WCAT_COLS (P2_COLS + OUT_FEAT)     // 576
#define WCAT_ELEMS (IN_FEAT * WCAT_COLS)   // 36864

#define SCAN_T 1024
#define SCAN_NB ((N_NODES_MAX + SCAN_T - 1) / SCAN_T)   // 98

// Scratch
__device__ __half g_proj2[(size_t)N_NODES_MAX * P2_COLS];   // ~102.4 MB
__device__ __half g_wcat[IN_FEAT * WCAT_COLS];
__device__ int    g_count[N_NODES_MAX];
__device__ int    g_offset[N_NODES_MAX];
__device__ int    g_cursor[N_NODES_MAX];
__device__ int    g_bsum[SCAN_NB];
__device__ int2   g_edata[N_EDGES_MAX];     // dst-sorted {src|etype<<20, norm}

// ---------------------------------------------------------------------------
// Prep kernel: zero counts + build Wcat (one launch)
// ---------------------------------------------------------------------------
__global__ void prep_kernel(const float* __restrict__ weight,
                            const float* __restrict__ w_comp,
                            const float* __restrict__ loop_w,
                            int n_nodes)
{
    int idx = blockIdx.x * blockDim.x + threadIdx.x;
    if (idx < n_nodes) g_count[idx] = 0;
    if (idx < WCAT_ELEMS) {
        int k = idx / WCAT_COLS;
        int n = idx % WCAT_COLS;
        float v;
        if (n < P2_COLS) {
            int r = n >> 6, o = n & 63;
            v = 0.0f;
            #pragma unroll
            for (int b = 0; b < NUM_BASES; ++b)
                v += w_comp[r * NUM_BASES + b] * weight[((size_t)b * 64 + k) * 64 + o];
        } else {
            v = loop_w[(size_t)k * 64 + (n - P2_COLS)];
        }
        g_wcat[idx] = __float2half_rn(v);
    }
}

// ---------------------------------------------------------------------------
__device__ __forceinline__ uint32_t smem_u32(const void* p) {
    return (uint32_t)__cvta_generic_to_shared(p);
}

#define LDSM_X4(r0, r1, r2, r3, addr)                                          \
    asm volatile("ldmatrix.sync.aligned.m8n8.x4.shared.b16 {%0,%1,%2,%3}, [%4];" \
                 : "=r"(r0), "=r"(r1), "=r"(r2), "=r"(r3) : "r"(addr))

#define LDSM_X4_T(r0, r1, r2, r3, addr)                                        \
    asm volatile("ldmatrix.sync.aligned.m8n8.x4.trans.shared.b16 {%0,%1,%2,%3}, [%4];" \
                 : "=r"(r0), "=r"(r1), "=r"(r2), "=r"(r3) : "r"(addr))

#define MMA_16816(d, a, b)                                                     \
    asm volatile("mma.sync.aligned.m16n8k16.row.col.f32.f16.f16.f32 "          \
                 "{%0,%1,%2,%3}, {%4,%5,%6,%7}, {%8,%9}, {%0,%1,%2,%3};"       \
                 : "+f"(d[0]), "+f"(d[1]), "+f"(d[2]), "+f"(d[3])              \
                 : "r"(a[0]), "r"(a[1]), "r"(a[2]), "r"(a[3]),                 \
                   "r"(b[0]), "r"(b[1]))

// ---------------------------------------------------------------------------
// Kernel A: proj2 (fp16) + out-init (fp32) via HMMA (R13 exact:
//   per-pass B, staged copy-out, embedded grid-stride dst-histogram)
// ---------------------------------------------------------------------------
#define SA_STRIDE 72
#define SBP_STRIDE 72
#define SS_STRIDE 72

#define SMEM_A_OFF 0
#define SMEM_B_OFF (128 * SA_STRIDE)
#define SMEM_S_OFF (128 * SA_STRIDE + 64 * SBP_STRIDE)
#define SMEM_HALVES (128 * SA_STRIDE + 64 * SBP_STRIDE + 128 * SS_STRIDE)
#define SMEM_BYTES (SMEM_HALVES * 2)   // 46080 B

__global__ __launch_bounds__(256, 3) void rgcn_mma_kernel(
    const float* __restrict__ feat,
    const float* __restrict__ h_bias,
    const int*   __restrict__ dst,
    float* __restrict__ out,
    int n_nodes, int n_edges)
{
    extern __shared__ __align__(16) __half dyn[];
    __half* sA = dyn + SMEM_A_OFF;
    __half* sB = dyn + SMEM_B_OFF;
    __half* sS = dyn + SMEM_S_OFF;

    const int tid = threadIdx.x;
    const int row0 = blockIdx.x * 128;
    const bool fullTile = (row0 + 128 <= n_nodes);

    // --- Embedded histogram: fire-and-forget REDs, independent of GEMM ---
    {
        int quads = (n_edges + 3) >> 2;
        for (int q = blockIdx.x * 256 + tid; q < quads; q += gridDim.x * 256) {
            int e0 = q * 4;
            if (e0 + 4 <= n_edges) {
                int4 d = __ldg((const int4*)(dst + e0));
                atomicAdd(&g_count[d.x], 1);
                atomicAdd(&g_count[d.y], 1);
                atomicAdd(&g_count[d.z], 1);
                atomicAdd(&g_count[d.w], 1);
            } else {
                for (int e = e0; e < n_edges; ++e)
                    atomicAdd(&g_count[__ldg(&dst[e])], 1);
            }
        }
    }

    // Load A tile (128 x 64), fp32 -> fp16
    #pragma unroll
    for (int i = tid; i < 128 * 32; i += 256) {
        int r = i >> 5;
        int cpair = i & 31;
        int row = row0 + r;
        float2 f = (row < n_nodes)
                     ? *(const float2*)&feat[(size_t)row * IN_FEAT + cpair * 2]
                     : make_float2(0.0f, 0.0f);
        *(__half2*)&sA[r * SA_STRIDE + cpair * 2] = __floats2half2_rn(f.x, f.y);
    }

    const int warp = tid >> 5;
    const int lane = tid & 31;
    const int wr = warp >> 1;
    const int wc = warp & 1;
    const int lrow = lane & 15;
    const int lcol = (lane >> 4) << 3;
    const int g   = lane >> 2;
    const int tig = lane & 3;

    for (int cp = 0; cp < 9; ++cp) {
        __syncthreads();
        #pragma unroll
        for (int i = tid; i < 512; i += 256) {
            int r = i >> 3;
            int ch = i & 7;
            *(uint4*)&sB[r * SBP_STRIDE + ch * 8] =
                *(const uint4*)&g_wcat[(size_t)r * WCAT_COLS + cp * 64 + ch * 8];
        }
        __syncthreads();

        float acc[2][4][4];
        #pragma unroll
        for (int mi = 0; mi < 2; ++mi)
            #pragma unroll
            for (int nj = 0; nj < 4; ++nj)
                #pragma unroll
                for (int q = 0; q < 4; ++q)
                    acc[mi][nj][q] = 0.0f;

        #pragma unroll
        for (int ks = 0; ks < 4; ++ks) {
            uint32_t a[2][4];
            #pragma unroll
            for (int mi = 0; mi < 2; ++mi) {
                const __half* p = &sA[(wr * 32 + mi * 16 + lrow) * SA_STRIDE
                                      + ks * 16 + lcol];
                LDSM_X4(a[mi][0], a[mi][1], a[mi][2], a[mi][3], smem_u32(p));
            }
            uint32_t b[4][2];
            #pragma unroll
            for (int np = 0; np < 2; ++np) {
                const __half* p = &sB[(ks * 16 + lrow) * SBP_STRIDE
                                      + wc * 32 + np * 16 + lcol];
                uint32_t r0, r1, r2, r3;
                LDSM_X4_T(r0, r1, r2, r3, smem_u32(p));
                b[np * 2 + 0][0] = r0; b[np * 2 + 0][1] = r1;
                b[np * 2 + 1][0] = r2; b[np * 2 + 1][1] = r3;
            }
            #pragma unroll
            for (int mi = 0; mi < 2; ++mi)
                #pragma unroll
                for (int nj = 0; nj < 4; ++nj)
                    MMA_16816(acc[mi][nj], a[mi], b[nj]);
        }

        if (cp < 8) {
            __syncthreads();
            #pragma unroll
            for (int mi = 0; mi < 2; ++mi) {
                int rta = wr * 32 + mi * 16 + g;
                int rtb = rta + 8;
                #pragma unroll
                for (int nj = 0; nj < 4; ++nj) {
                    int col = wc * 32 + nj * 8 + tig * 2;
                    *(__half2*)&sS[rta * SS_STRIDE + col] =
                        __floats2half2_rn(acc[mi][nj][0], acc[mi][nj][1]);
                    *(__half2*)&sS[rtb * SS_STRIDE + col] =
                        __floats2half2_rn(acc[mi][nj][2], acc[mi][nj][3]);
                }
            }
            __syncthreads();
            if (fullTile) {
                #pragma unroll
                for (int i = tid; i < 1024; i += 256) {
                    int r = i >> 3;
                    int ch = i & 7;
                    uint4 v = *(const uint4*)&sS[r * SS_STRIDE + ch * 8];
                    *(uint4*)&g_proj2[(size_t)(row0 + r) * P2_COLS
                                      + cp * OUT_FEAT + ch * 8] = v;
                }
            } else {
                #pragma unroll
                for (int i = tid; i < 1024; i += 256) {
                    int r = i >> 3;
                    int ch = i & 7;
                    int row = row0 + r;
                    if (row < n_nodes) {
                        uint4 v = *(const uint4*)&sS[r * SS_STRIDE + ch * 8];
                        *(uint4*)&g_proj2[(size_t)row * P2_COLS
                                          + cp * OUT_FEAT + ch * 8] = v;
                    }
                }
            }
        } else {
            #pragma unroll
            for (int mi = 0; mi < 2; ++mi) {
                int ra = row0 + wr * 32 + mi * 16 + g;
                int rb = ra + 8;
                #pragma unroll
                for (int nj = 0; nj < 4; ++nj) {
                    int col = wc * 32 + nj * 8 + tig * 2;
                    float b0 = h_bias[col];
                    float b1 = h_bias[col + 1];
                    if (ra < n_nodes)
                        *(float2*)&out[(size_t)ra * OUT_FEAT + col] =
                            make_float2(acc[mi][nj][0] + b0, acc[mi][nj][1] + b1);
                    if (rb < n_nodes)
                        *(float2*)&out[(size_t)rb * OUT_FEAT + col] =
                            make_float2(acc[mi][nj][2] + b0, acc[mi][nj][3] + b1);
                }
            }
        }
    }
}

// ---------------------------------------------------------------------------
// Scan kernels (R13-proven 3-kernel chain)
// ---------------------------------------------------------------------------
__global__ __launch_bounds__(SCAN_T) void scan_local_kernel(int n_nodes)
{
    __shared__ int sh[SCAN_T];
    int i = blockIdx.x * SCAN_T + threadIdx.x;
    int c = (i < n_nodes) ? g_count[i] : 0;
    sh[threadIdx.x] = c;
    __syncthreads();
    #pragma unroll
    for (int off = 1; off < SCAN_T; off <<= 1) {
        int v = (threadIdx.x >= off) ? sh[threadIdx.x - off] : 0;
        __syncthreads();
        sh[threadIdx.x] += v;
        __syncthreads();
    }
    if (i < n_nodes) g_offset[i] = sh[threadIdx.x] - c;
    if (threadIdx.x == SCAN_T - 1) g_bsum[blockIdx.x] = sh[SCAN_T - 1];
}

__global__ __launch_bounds__(128) void scan_bsum_kernel(int nb)
{
    __shared__ int sh[128];
    int t = threadIdx.x;
    int c = (t < nb) ? g_bsum[t] : 0;
    sh[t] = c;
    __syncthreads();
    #pragma unroll
    for (int off = 1; off < 128; off <<= 1) {
        int v = (t >= off) ? sh[t - off] : 0;
        __syncthreads();
        sh[t] += v;
        __syncthreads();
    }
    if (t < nb) g_bsum[t] = sh[t] - c;
}

__global__ __launch_bounds__(SCAN_T) void scan_add_kernel(int n_nodes)
{
    int i = blockIdx.x * SCAN_T + threadIdx.x;
    if (i < n_nodes) {
        int o = g_offset[i] + g_bsum[blockIdx.x];
        g_offset[i] = o;
        g_cursor[i] = o;
    }
}

// ---------------------------------------------------------------------------
// Kernel 3: scatter, 8 edges/thread (deeper ATOMG MLP)
// ---------------------------------------------------------------------------
__global__ void scatter_kernel(const int* __restrict__ src,
                               const int* __restrict__ dst,
                               const int* __restrict__ etypes,
                               const float* __restrict__ norm,
                               int n_edges)
{
    int i = blockIdx.x * blockDim.x + threadIdx.x;
    int e0 = i * 8;
    if (e0 + 8 <= n_edges) {
        int4 s0 = __ldg((const int4*)(src + e0));
        int4 s1 = __ldg((const int4*)(src + e0 + 4));
        int4 d0 = __ldg((const int4*)(dst + e0));
        int4 d1 = __ldg((const int4*)(dst + e0 + 4));
        int4 t0 = __ldg((const int4*)(etypes + e0));
        int4 t1 = __ldg((const int4*)(etypes + e0 + 4));
        float4 n0 = __ldg((const float4*)(norm + e0));
        float4 n1 = __ldg((const float4*)(norm + e0 + 4));

        int p0 = atomicAdd(&g_cursor[d0.x], 1);
        int p1 = atomicAdd(&g_cursor[d0.y], 1);
        int p2 = atomicAdd(&g_cursor[d0.z], 1);
        int p3 = atomicAdd(&g_cursor[d0.w], 1);
        int p4 = atomicAdd(&g_cursor[d1.x], 1);
        int p5 = atomicAdd(&g_cursor[d1.y], 1);
        int p6 = atomicAdd(&g_cursor[d1.z], 1);
        int p7 = atomicAdd(&g_cursor[d1.w], 1);

        g_edata[p0] = make_int2(s0.x | (t0.x << 20), __float_as_int(n0.x));
        g_edata[p1] = make_int2(s0.y | (t0.y << 20), __float_as_int(n0.y));
        g_edata[p2] = make_int2(s0.z | (t0.z << 20), __float_as_int(n0.z));
        g_edata[p3] = make_int2(s0.w | (t0.w << 20), __float_as_int(n0.w));
        g_edata[p4] = make_int2(s1.x | (t1.x << 20), __float_as_int(n1.x));
        g_edata[p5] = make_int2(s1.y | (t1.y << 20), __float_as_int(n1.y));
        g_edata[p6] = make_int2(s1.z | (t1.z << 20), __float_as_int(n1.z));
        g_edata[p7] = make_int2(s1.w | (t1.w << 20), __float_as_int(n1.w));
    } else if (e0 < n_edges) {
        for (int e = e0; e < n_edges; ++e) {
            int d = __ldg(&dst[e]);
            int pos = atomicAdd(&g_cursor[d], 1);
            g_edata[pos] = make_int2(__ldg(&src[e]) | (__ldg(&etypes[e]) << 20),
                                     __float_as_int(__ldg(&norm[e])));
        }
    }
}

// ---------------------------------------------------------------------------
// Kernel 4: per-node aggregation, 8 lanes/node, uint4 gathers (R8 exact)
// ---------------------------------------------------------------------------
__device__ __forceinline__ void acc_msg(float4& a, float4& b, uint4 raw, float nm)
{
    float2 f0 = __half22float2(*reinterpret_cast<__half2*>(&raw.x));
    float2 f1 = __half22float2(*reinterpret_cast<__half2*>(&raw.y));
    float2 f2 = __half22float2(*reinterpret_cast<__half2*>(&raw.z));
    float2 f3 = __half22float2(*reinterpret_cast<__half2*>(&raw.w));
    a.x += f0.x * nm; a.y += f0.y * nm; a.z += f1.x * nm; a.w += f1.y * nm;
    b.x += f2.x * nm; b.y += f2.y * nm; b.z += f3.x * nm; b.w += f3.y * nm;
}

__global__ __launch_bounds__(256) void agg_kernel(
    float* __restrict__ out, int n_nodes)
{
    int gidx = blockIdx.x * 256 + threadIdx.x;
    int node = gidx >> 3;
    int lane = gidx & 7;
    if (node >= n_nodes) return;

    int start = __ldg(&g_offset[node]);
    int deg   = __ldg(&g_count[node]);

    float4 accA = *(float4*)&out[(size_t)node * OUT_FEAT + lane * 8];
    float4 accB = *(float4*)&out[(size_t)node * OUT_FEAT + lane * 8 + 4];

    int j = 0;
    for (; j + 4 <= deg; j += 4) {
        int2 e0 = __ldg(&g_edata[start + j + 0]);
        int2 e1 = __ldg(&g_edata[start + j + 1]);
        int2 e2 = __ldg(&g_edata[start + j + 2]);
        int2 e3 = __ldg(&g_edata[start + j + 3]);
        uint4 r0 = __ldg((const uint4*)(g_proj2 +
            ((size_t)(e0.x & 0xFFFFF) * P2_COLS + (e0.x >> 20) * OUT_FEAT + lane * 8)));
        uint4 r1 = __ldg((const uint4*)(g_proj2 +
            ((size_t)(e1.x & 0xFFFFF) * P2_COLS + (e1.x >> 20) * OUT_FEAT + lane * 8)));
        uint4 r2 = __ldg((const uint4*)(g_proj2 +
            ((size_t)(e2.x & 0xFFFFF) * P2_COLS + (e2.x >> 20) * OUT_FEAT + lane * 8)));
        uint4 r3 = __ldg((const uint4*)(g_proj2 +
            ((size_t)(e3.x & 0xFFFFF) * P2_COLS + (e3.x >> 20) * OUT_FEAT + lane * 8)));
        acc_msg(accA, accB, r0, __int_as_float(e0.y));
        acc_msg(accA, accB, r1, __int_as_float(e1.y));
        acc_msg(accA, accB, r2, __int_as_float(e2.y));
        acc_msg(accA, accB, r3, __int_as_float(e3.y));
    }
    for (; j < deg; ++j) {
        int2 ed = __ldg(&g_edata[start + j]);
        uint4 raw = __ldg((const uint4*)(g_proj2 +
            ((size_t)(ed.x & 0xFFFFF) * P2_COLS + (ed.x >> 20) * OUT_FEAT + lane * 8)));
        acc_msg(accA, accB, raw, __int_as_float(ed.y));
    }

    *(float4*)&out[(size_t)node * OUT_FEAT + lane * 8]     = accA;
    *(float4*)&out[(size_t)node * OUT_FEAT + lane * 8 + 4] = accB;
}

// ---------------------------------------------------------------------------
extern "C" void kernel_launch(void* const* d_in, const int* in_sizes, int n_in,
                              void* d_out, int out_size)
{
    const float* feat    = (const float*)d_in[0];
    const int*   src     = (const int*)d_in[1];
    const int*   dst     = (const int*)d_in[2];
    const int*   etypes  = (const int*)d_in[3];
    const float* norm    = (const float*)d_in[4];
    const float* weight  = (const float*)d_in[5];
    const float* w_comp  = (const float*)d_in[6];
    const float* h_bias  = (const float*)d_in[7];
    const float* loop_w  = (const float*)d_in[8];
    float*       out     = (float*)d_out;

    int n_nodes = in_sizes[0] / IN_FEAT;
    int n_edges = in_sizes[1];

    static bool attrSet = false;
    if (!attrSet) {
        cudaFuncSetAttribute(rgcn_mma_kernel,
                             cudaFuncAttributeMaxDynamicSharedMemorySize, SMEM_BYTES);
        attrSet = true;
    }

    // Phase 0: zero counters + Wcat (one launch)
    int prep_elems = (n_nodes > WCAT_ELEMS) ? n_nodes : WCAT_ELEMS;
    prep_kernel<<<(prep_elems + 255) / 256, 256>>>(weight, w_comp, loop_w, n_nodes);

    // Phase 1: HMMA GEMM with embedded dst-histogram
    rgcn_mma_kernel<<<(n_nodes + 127) / 128, 256, SMEM_BYTES>>>(
        feat, h_bias, dst, out, n_nodes, n_edges);

    // Phase 2: scan (proven 3-kernel chain) + scatter (8 edges/thread)
    int nb = (n_nodes + SCAN_T - 1) / SCAN_T;
    scan_local_kernel<<<nb, SCAN_T>>>(n_nodes);
    scan_bsum_kernel<<<1, 128>>>(nb);
    scan_add_kernel<<<nb, SCAN_T>>>(n_nodes);
    int sthreads = (n_edges + 7) / 8;
    scatter_kernel<<<(sthreads + 255) / 256, 256>>>(src, dst, etypes, norm, n_edges);

    // Phase 3: atomic-free aggregation
    long long total_threads = (long long)n_nodes * 8;
    agg_kernel<<<(int)((total_threads + 255) / 256), 256>>>(out, n_nodes);
}

// round 16
// speedup vs baseline: 1.0985x; 1.0316x over previous
#include <cuda_runtime.h>
#include <cuda_fp16.h>
#include <stdint.h>

#define N_NODES_MAX 100000
#define N_EDGES_MAX 1600000
#define IN_FEAT 64
#define OUT_FEAT 64
#define NUM_BASES 4
#define NUM_RELS 8
#define P2_COLS (NUM_RELS * OUT_FEAT)      // 512
#define WCAT_COLS (P2_COLS + OUT_FEAT)     // 576
#define WCAT_ELEMS (IN_FEAT * WCAT_COLS)   // 36864

#define SCAN_T 1024
#define SCAN_NB ((N_NODES_MAX + SCAN_T - 1) / SCAN_T)   // 98

// Scratch
__device__ __half g_proj2[(size_t)N_NODES_MAX * P2_COLS];   // ~102.4 MB
__device__ __half g_wcat[IN_FEAT * WCAT_COLS];
__device__ int    g_count[N_NODES_MAX];
__device__ int    g_offset[N_NODES_MAX];
__device__ int    g_cursor[N_NODES_MAX];
__device__ int    g_bsum[SCAN_NB];
__device__ int2   g_edata[N_EDGES_MAX];     // dst-sorted {src|etype<<20, norm}

// ---------------------------------------------------------------------------
// Prep kernel: zero counts + build Wcat (one launch)
// ---------------------------------------------------------------------------
__global__ void prep_kernel(const float* __restrict__ weight,
                            const float* __restrict__ w_comp,
                            const float* __restrict__ loop_w,
                            int n_nodes)
{
    int idx = blockIdx.x * blockDim.x + threadIdx.x;
    if (idx < n_nodes) g_count[idx] = 0;
    if (idx < WCAT_ELEMS) {
        int k = idx / WCAT_COLS;
        int n = idx % WCAT_COLS;
        float v;
        if (n < P2_COLS) {
            int r = n >> 6, o = n & 63;
            v = 0.0f;
            #pragma unroll
            for (int b = 0; b < NUM_BASES; ++b)
                v += w_comp[r * NUM_BASES + b] * weight[((size_t)b * 64 + k) * 64 + o];
        } else {
            v = loop_w[(size_t)k * 64 + (n - P2_COLS)];
        }
        g_wcat[idx] = __float2half_rn(v);
    }
}

// ---------------------------------------------------------------------------
__device__ __forceinline__ uint32_t smem_u32(const void* p) {
    return (uint32_t)__cvta_generic_to_shared(p);
}

#define LDSM_X4(r0, r1, r2, r3, addr)                                          \
    asm volatile("ldmatrix.sync.aligned.m8n8.x4.shared.b16 {%0,%1,%2,%3}, [%4];" \
                 : "=r"(r0), "=r"(r1), "=r"(r2), "=r"(r3) : "r"(addr))

#define LDSM_X4_T(r0, r1, r2, r3, addr)                                        \
    asm volatile("ldmatrix.sync.aligned.m8n8.x4.trans.shared.b16 {%0,%1,%2,%3}, [%4];" \
                 : "=r"(r0), "=r"(r1), "=r"(r2), "=r"(r3) : "r"(addr))

#define MMA_16816(d, a, b)                                                     \
    asm volatile("mma.sync.aligned.m16n8k16.row.col.f32.f16.f16.f32 "          \
                 "{%0,%1,%2,%3}, {%4,%5,%6,%7}, {%8,%9}, {%0,%1,%2,%3};"       \
                 : "+f"(d[0]), "+f"(d[1]), "+f"(d[2]), "+f"(d[3])              \
                 : "r"(a[0]), "r"(a[1]), "r"(a[2]), "r"(a[3]),                 \
                   "r"(b[0]), "r"(b[1]))

// ---------------------------------------------------------------------------
// Kernel A: proj2 (fp16) + out-init (fp32) via HMMA (R13 exact:
//   per-pass B, staged copy-out, embedded grid-stride dst-histogram)
// ---------------------------------------------------------------------------
#define SA_STRIDE 72
#define SBP_STRIDE 72
#define SS_STRIDE 72

#define SMEM_A_OFF 0
#define SMEM_B_OFF (128 * SA_STRIDE)
#define SMEM_S_OFF (128 * SA_STRIDE + 64 * SBP_STRIDE)
#define SMEM_HALVES (128 * SA_STRIDE + 64 * SBP_STRIDE + 128 * SS_STRIDE)
#define SMEM_BYTES (SMEM_HALVES * 2)   // 46080 B

__global__ __launch_bounds__(256, 3) void rgcn_mma_kernel(
    const float* __restrict__ feat,
    const float* __restrict__ h_bias,
    const int*   __restrict__ dst,
    float* __restrict__ out,
    int n_nodes, int n_edges)
{
    extern __shared__ __align__(16) __half dyn[];
    __half* sA = dyn + SMEM_A_OFF;
    __half* sB = dyn + SMEM_B_OFF;
    __half* sS = dyn + SMEM_S_OFF;

    const int tid = threadIdx.x;
    const int row0 = blockIdx.x * 128;
    const bool fullTile = (row0 + 128 <= n_nodes);

    // --- Embedded histogram: fire-and-forget REDs, independent of GEMM ---
    {
        int quads = (n_edges + 3) >> 2;
        for (int q = blockIdx.x * 256 + tid; q < quads; q += gridDim.x * 256) {
            int e0 = q * 4;
            if (e0 + 4 <= n_edges) {
                int4 d = __ldg((const int4*)(dst + e0));
                atomicAdd(&g_count[d.x], 1);
                atomicAdd(&g_count[d.y], 1);
                atomicAdd(&g_count[d.z], 1);
                atomicAdd(&g_count[d.w], 1);
            } else {
                for (int e = e0; e < n_edges; ++e)
                    atomicAdd(&g_count[__ldg(&dst[e])], 1);
            }
        }
    }

    // Load A tile (128 x 64), fp32 -> fp16
    #pragma unroll
    for (int i = tid; i < 128 * 32; i += 256) {
        int r = i >> 5;
        int cpair = i & 31;
        int row = row0 + r;
        float2 f = (row < n_nodes)
                     ? *(const float2*)&feat[(size_t)row * IN_FEAT + cpair * 2]
                     : make_float2(0.0f, 0.0f);
        *(__half2*)&sA[r * SA_STRIDE + cpair * 2] = __floats2half2_rn(f.x, f.y);
    }

    const int warp = tid >> 5;
    const int lane = tid & 31;
    const int wr = warp >> 1;
    const int wc = warp & 1;
    const int lrow = lane & 15;
    const int lcol = (lane >> 4) << 3;
    const int g   = lane >> 2;
    const int tig = lane & 3;

    for (int cp = 0; cp < 9; ++cp) {
        __syncthreads();
        #pragma unroll
        for (int i = tid; i < 512; i += 256) {
            int r = i >> 3;
            int ch = i & 7;
            *(uint4*)&sB[r * SBP_STRIDE + ch * 8] =
                *(const uint4*)&g_wcat[(size_t)r * WCAT_COLS + cp * 64 + ch * 8];
        }
        __syncthreads();

        float acc[2][4][4];
        #pragma unroll
        for (int mi = 0; mi < 2; ++mi)
            #pragma unroll
            for (int nj = 0; nj < 4; ++nj)
                #pragma unroll
                for (int q = 0; q < 4; ++q)
                    acc[mi][nj][q] = 0.0f;

        #pragma unroll
        for (int ks = 0; ks < 4; ++ks) {
            uint32_t a[2][4];
            #pragma unroll
            for (int mi = 0; mi < 2; ++mi) {
                const __half* p = &sA[(wr * 32 + mi * 16 + lrow) * SA_STRIDE
                                      + ks * 16 + lcol];
                LDSM_X4(a[mi][0], a[mi][1], a[mi][2], a[mi][3], smem_u32(p));
            }
            uint32_t b[4][2];
            #pragma unroll
            for (int np = 0; np < 2; ++np) {
                const __half* p = &sB[(ks * 16 + lrow) * SBP_STRIDE
                                      + wc * 32 + np * 16 + lcol];
                uint32_t r0, r1, r2, r3;
                LDSM_X4_T(r0, r1, r2, r3, smem_u32(p));
                b[np * 2 + 0][0] = r0; b[np * 2 + 0][1] = r1;
                b[np * 2 + 1][0] = r2; b[np * 2 + 1][1] = r3;
            }
            #pragma unroll
            for (int mi = 0; mi < 2; ++mi)
                #pragma unroll
                for (int nj = 0; nj < 4; ++nj)
                    MMA_16816(acc[mi][nj], a[mi], b[nj]);
        }

        if (cp < 8) {
            __syncthreads();
            #pragma unroll
            for (int mi = 0; mi < 2; ++mi) {
                int rta = wr * 32 + mi * 16 + g;
                int rtb = rta + 8;
                #pragma unroll
                for (int nj = 0; nj < 4; ++nj) {
                    int col = wc * 32 + nj * 8 + tig * 2;
                    *(__half2*)&sS[rta * SS_STRIDE + col] =
                        __floats2half2_rn(acc[mi][nj][0], acc[mi][nj][1]);
                    *(__half2*)&sS[rtb * SS_STRIDE + col] =
                        __floats2half2_rn(acc[mi][nj][2], acc[mi][nj][3]);
                }
            }
            __syncthreads();
            if (fullTile) {
                #pragma unroll
                for (int i = tid; i < 1024; i += 256) {
                    int r = i >> 3;
                    int ch = i & 7;
                    uint4 v = *(const uint4*)&sS[r * SS_STRIDE + ch * 8];
                    *(uint4*)&g_proj2[(size_t)(row0 + r) * P2_COLS
                                      + cp * OUT_FEAT + ch * 8] = v;
                }
            } else {
                #pragma unroll
                for (int i = tid; i < 1024; i += 256) {
                    int r = i >> 3;
                    int ch = i & 7;
                    int row = row0 + r;
                    if (row < n_nodes) {
                        uint4 v = *(const uint4*)&sS[r * SS_STRIDE + ch * 8];
                        *(uint4*)&g_proj2[(size_t)row * P2_COLS
                                          + cp * OUT_FEAT + ch * 8] = v;
                    }
                }
            }
        } else {
            #pragma unroll
            for (int mi = 0; mi < 2; ++mi) {
                int ra = row0 + wr * 32 + mi * 16 + g;
                int rb = ra + 8;
                #pragma unroll
                for (int nj = 0; nj < 4; ++nj) {
                    int col = wc * 32 + nj * 8 + tig * 2;
                    float b0 = h_bias[col];
                    float b1 = h_bias[col + 1];
                    if (ra < n_nodes)
                        *(float2*)&out[(size_t)ra * OUT_FEAT + col] =
                            make_float2(acc[mi][nj][0] + b0, acc[mi][nj][1] + b1);
                    if (rb < n_nodes)
                        *(float2*)&out[(size_t)rb * OUT_FEAT + col] =
                            make_float2(acc[mi][nj][2] + b0, acc[mi][nj][3] + b1);
                }
            }
        }
    }
}

// ---------------------------------------------------------------------------
// Scan: 2 kernels. scan_local produces per-block partials + block sums;
// scan_add computes each block's base by warp-reducing g_bsum (<=97 ints).
// ---------------------------------------------------------------------------
__global__ __launch_bounds__(SCAN_T) void scan_local_kernel(int n_nodes)
{
    __shared__ int sh[SCAN_T];
    int i = blockIdx.x * SCAN_T + threadIdx.x;
    int c = (i < n_nodes) ? g_count[i] : 0;
    sh[threadIdx.x] = c;
    __syncthreads();
    #pragma unroll
    for (int off = 1; off < SCAN_T; off <<= 1) {
        int v = (threadIdx.x >= off) ? sh[threadIdx.x - off] : 0;
        __syncthreads();
        sh[threadIdx.x] += v;
        __syncthreads();
    }
    if (i < n_nodes) g_offset[i] = sh[threadIdx.x] - c;
    if (threadIdx.x == SCAN_T - 1) g_bsum[blockIdx.x] = sh[SCAN_T - 1];
}

__global__ __launch_bounds__(SCAN_T) void scan_add_kernel(int n_nodes)
{
    __shared__ int s_base;
    if (threadIdx.x < 32) {
        int sum = 0;
        for (int j = threadIdx.x; j < blockIdx.x; j += 32)
            sum += g_bsum[j];
        #pragma unroll
        for (int off = 16; off > 0; off >>= 1)
            sum += __shfl_down_sync(0xFFFFFFFFu, sum, off);
        if (threadIdx.x == 0) s_base = sum;
    }
    __syncthreads();
    int i = blockIdx.x * SCAN_T + threadIdx.x;
    if (i < n_nodes) {
        int o = g_offset[i] + s_base;
        g_offset[i] = o;
        g_cursor[i] = o;
    }
}

// ---------------------------------------------------------------------------
// Kernel 3: scatter edges into dst-sorted order (R13 exact: 4 edges/thread)
// ---------------------------------------------------------------------------
__global__ void scatter_kernel(const int* __restrict__ src,
                               const int* __restrict__ dst,
                               const int* __restrict__ etypes,
                               const float* __restrict__ norm,
                               int n_edges)
{
    int i = blockIdx.x * blockDim.x + threadIdx.x;
    int e0 = i * 4;
    if (e0 + 4 <= n_edges) {
        int4 s = __ldg((const int4*)(src + e0));
        int4 d = __ldg((const int4*)(dst + e0));
        int4 t = __ldg((const int4*)(etypes + e0));
        float4 nm = __ldg((const float4*)(norm + e0));
        int p0 = atomicAdd(&g_cursor[d.x], 1);
        int p1 = atomicAdd(&g_cursor[d.y], 1);
        int p2 = atomicAdd(&g_cursor[d.z], 1);
        int p3 = atomicAdd(&g_cursor[d.w], 1);
        g_edata[p0] = make_int2(s.x | (t.x << 20), __float_as_int(nm.x));
        g_edata[p1] = make_int2(s.y | (t.y << 20), __float_as_int(nm.y));
        g_edata[p2] = make_int2(s.z | (t.z << 20), __float_as_int(nm.z));
        g_edata[p3] = make_int2(s.w | (t.w << 20), __float_as_int(nm.w));
    } else if (e0 < n_edges) {
        for (int e = e0; e < n_edges; ++e) {
            int d = __ldg(&dst[e]);
            int pos = atomicAdd(&g_cursor[d], 1);
            g_edata[pos] = make_int2(__ldg(&src[e]) | (__ldg(&etypes[e]) << 20),
                                     __float_as_int(__ldg(&norm[e])));
        }
    }
}

// ---------------------------------------------------------------------------
// Kernel 4: per-node aggregation, 8 lanes/node, uint4 gathers (R8 exact)
// ---------------------------------------------------------------------------
__device__ __forceinline__ void acc_msg(float4& a, float4& b, uint4 raw, float nm)
{
    float2 f0 = __half22float2(*reinterpret_cast<__half2*>(&raw.x));
    float2 f1 = __half22float2(*reinterpret_cast<__half2*>(&raw.y));
    float2 f2 = __half22float2(*reinterpret_cast<__half2*>(&raw.z));
    float2 f3 = __half22float2(*reinterpret_cast<__half2*>(&raw.w));
    a.x += f0.x * nm; a.y += f0.y * nm; a.z += f1.x * nm; a.w += f1.y * nm;
    b.x += f2.x * nm; b.y += f2.y * nm; b.z += f3.x * nm; b.w += f3.y * nm;
}

__global__ __launch_bounds__(256) void agg_kernel(
    float* __restrict__ out, int n_nodes)
{
    int gidx = blockIdx.x * 256 + threadIdx.x;
    int node = gidx >> 3;
    int lane = gidx & 7;
    if (node >= n_nodes) return;

    int start = __ldg(&g_offset[node]);
    int deg   = __ldg(&g_count[node]);

    float4 accA = *(float4*)&out[(size_t)node * OUT_FEAT + lane * 8];
    float4 accB = *(float4*)&out[(size_t)node * OUT_FEAT + lane * 8 + 4];

    int j = 0;
    for (; j + 4 <= deg; j += 4) {
        int2 e0 = __ldg(&g_edata[start + j + 0]);
        int2 e1 = __ldg(&g_edata[start + j + 1]);
        int2 e2 = __ldg(&g_edata[start + j + 2]);
        int2 e3 = __ldg(&g_edata[start + j + 3]);
        uint4 r0 = __ldg((const uint4*)(g_proj2 +
            ((size_t)(e0.x & 0xFFFFF) * P2_COLS + (e0.x >> 20) * OUT_FEAT + lane * 8)));
        uint4 r1 = __ldg((const uint4*)(g_proj2 +
            ((size_t)(e1.x & 0xFFFFF) * P2_COLS + (e1.x >> 20) * OUT_FEAT + lane * 8)));
        uint4 r2 = __ldg((const uint4*)(g_proj2 +
            ((size_t)(e2.x & 0xFFFFF) * P2_COLS + (e2.x >> 20) * OUT_FEAT + lane * 8)));
        uint4 r3 = __ldg((const uint4*)(g_proj2 +
            ((size_t)(e3.x & 0xFFFFF) * P2_COLS + (e3.x >> 20) * OUT_FEAT + lane * 8)));
        acc_msg(accA, accB, r0, __int_as_float(e0.y));
        acc_msg(accA, accB, r1, __int_as_float(e1.y));
        acc_msg(accA, accB, r2, __int_as_float(e2.y));
        acc_msg(accA, accB, r3, __int_as_float(e3.y));
    }
    for (; j < deg; ++j) {
        int2 ed = __ldg(&g_edata[start + j]);
        uint4 raw = __ldg((const uint4*)(g_proj2 +
            ((size_t)(ed.x & 0xFFFFF) * P2_COLS + (ed.x >> 20) * OUT_FEAT + lane * 8)));
        acc_msg(accA, accB, raw, __int_as_float(ed.y));
    }

    *(float4*)&out[(size_t)node * OUT_FEAT + lane * 8]     = accA;
    *(float4*)&out[(size_t)node * OUT_FEAT + lane * 8 + 4] = accB;
}

// ---------------------------------------------------------------------------
extern "C" void kernel_launch(void* const* d_in, const int* in_sizes, int n_in,
                              void* d_out, int out_size)
{
    const float* feat    = (const float*)d_in[0];
    const int*   src     = (const int*)d_in[1];
    const int*   dst     = (const int*)d_in[2];
    const int*   etypes  = (const int*)d_in[3];
    const float* norm    = (const float*)d_in[4];
    const float* weight  = (const float*)d_in[5];
    const float* w_comp  = (const float*)d_in[6];
    const float* h_bias  = (const float*)d_in[7];
    const float* loop_w  = (const float*)d_in[8];
    float*       out     = (float*)d_out;

    int n_nodes = in_sizes[0] / IN_FEAT;
    int n_edges = in_sizes[1];

    static bool attrSet = false;
    if (!attrSet) {
        cudaFuncSetAttribute(rgcn_mma_kernel,
                             cudaFuncAttributeMaxDynamicSharedMemorySize, SMEM_BYTES);
        attrSet = true;
    }

    // Phase 0: zero counters + Wcat (one launch)
    int prep_elems = (n_nodes > WCAT_ELEMS) ? n_nodes : WCAT_ELEMS;
    prep_kernel<<<(prep_elems + 255) / 256, 256>>>(weight, w_comp, loop_w, n_nodes);

    // Phase 1: HMMA GEMM with embedded dst-histogram
    rgcn_mma_kernel<<<(n_nodes + 127) / 128, 256, SMEM_BYTES>>>(
        feat, h_bias, dst, out, n_nodes, n_edges);

    // Phase 2: scan (2 kernels) + scatter (4 edges/thread)
    int nb = (n_nodes + SCAN_T - 1) / SCAN_T;
    scan_local_kernel<<<nb, SCAN_T>>>(n_nodes);
    scan_add_kernel<<<nb, SCAN_T>>>(n_nodes);
    int hthreads = (n_edges + 3) / 4;
    scatter_kernel<<<(hthreads + 255) / 256, 256>>>(src, dst, etypes, norm, n_edges);

    // Phase 3: atomic-free aggregation
    long long total_threads = (long long)n_nodes * 8;
    agg_kernel<<<(int)((total_threads + 255) / 256), 256>>>(out, n_nodes);
}